// round 16
// baseline (speedup 1.0000x reference)
#include <cuda_runtime.h>
#include <cuda_fp16.h>
#include <mma.h>
#include <cstdint>
#include <math.h>

using namespace nvcuda;

// Problem constants
static constexpr int B_  = 2;
static constexpr int N_  = 2048;
static constexpr int C_  = 1024;
static constexpr int H_  = 16;
static constexpr int D_  = 64;
static constexpr int DFF = 4096;
static constexpr int M_  = B_ * N_;
static constexpr long long XSZ   = (long long)B_ * N_ * C_;
static constexpr long long ATTNSZ= (long long)B_ * H_ * N_ * N_;

// ---------------- scratch (device globals) ----------------
__device__ __align__(256) float g_x1 [M_ * C_];
__device__ __align__(256) float g_attn_fallback[ATTNSZ];
__device__ __align__(256) __half g_xn [M_ * C_];
__device__ __align__(256) __half g_qkv[M_ * 3 * C_];
__device__ __align__(256) __half g_ctx[M_ * C_];
__device__ __align__(256) __half g_hn [M_ * C_];
__device__ __align__(256) __half g_ff [M_ * DFF];
__device__ __align__(256) __half g_ap [ATTNSZ];      // fp16 softmax probs
__device__ __align__(256) __half g_wqkv[3 * C_ * C_];
__device__ __align__(256) __half g_wproj[C_ * C_];
__device__ __align__(256) __half g_wfc1[DFF * C_];
__device__ __align__(256) __half g_wfc2[C_ * DFF];

// ---------------- cp.async helpers ----------------
__device__ __forceinline__ void cp16(void* sdst, const void* gsrc) {
    uint32_t s = (uint32_t)__cvta_generic_to_shared(sdst);
    asm volatile("cp.async.cg.shared.global [%0], [%1], 16;" :: "r"(s), "l"(gsrc));
}
__device__ __forceinline__ void cp_commit() {
    asm volatile("cp.async.commit_group;" ::: "memory");
}
template <int N>
__device__ __forceinline__ void cp_wait() {
    asm volatile("cp.async.wait_group %0;" :: "n"(N) : "memory");
}

// ---------------- block reductions ----------------
__device__ __forceinline__ float blockReduceSum(float val, float* shbuf) {
    int lane = threadIdx.x & 31, wid = threadIdx.x >> 5;
#pragma unroll
    for (int o = 16; o > 0; o >>= 1) val += __shfl_xor_sync(0xffffffffu, val, o);
    if (lane == 0) shbuf[wid] = val;
    __syncthreads();
    if (wid == 0) {
        val = (lane < 8) ? shbuf[lane] : 0.0f;
#pragma unroll
        for (int o = 4; o > 0; o >>= 1) val += __shfl_xor_sync(0xffffffffu, val, o);
        if (lane == 0) shbuf[0] = val;
    }
    __syncthreads();
    float r = shbuf[0];
    __syncthreads();
    return r;
}
__device__ __forceinline__ float blockReduceMax(float val, float* shbuf) {
    int lane = threadIdx.x & 31, wid = threadIdx.x >> 5;
#pragma unroll
    for (int o = 16; o > 0; o >>= 1) val = fmaxf(val, __shfl_xor_sync(0xffffffffu, val, o));
    if (lane == 0) shbuf[wid] = val;
    __syncthreads();
    if (wid == 0) {
        val = (lane < 8) ? shbuf[lane] : -INFINITY;
#pragma unroll
        for (int o = 4; o > 0; o >>= 1) val = fmaxf(val, __shfl_xor_sync(0xffffffffu, val, o));
        if (lane == 0) shbuf[0] = val;
    }
    __syncthreads();
    float r = shbuf[0];
    __syncthreads();
    return r;
}

// ---------------- layernorm -> fp16 ----------------
__global__ __launch_bounds__(256)
void ln_h_kernel(const float* __restrict__ x, const float* __restrict__ g,
                 const float* __restrict__ b, __half* __restrict__ out) {
    __shared__ float sh[8];
    long long row = blockIdx.x;
    const float* xr = x + row * C_;
    int t = threadIdx.x;
    float v[4];
    float s = 0.0f;
#pragma unroll
    for (int i = 0; i < 4; i++) { v[i] = xr[t + i * 256]; s += v[i]; }
    s = blockReduceSum(s, sh);
    float mu = s * (1.0f / C_);
    float var = 0.0f;
#pragma unroll
    for (int i = 0; i < 4; i++) { float d = v[i] - mu; var += d * d; }
    var = blockReduceSum(var, sh);
    float r = rsqrtf(var * (1.0f / C_) + 1e-5f);
#pragma unroll
    for (int i = 0; i < 4; i++) {
        int c = t + i * 256;
        out[row * C_ + c] = __float2half_rn((v[i] - mu) * r * g[c] + b[c]);
    }
}

// ---------------- softmax: fp32 out + fp16 probs ----------------
__global__ __launch_bounds__(256)
void softmax_h_kernel(float* __restrict__ attn, __half* __restrict__ probs) {
    __shared__ float sh[8];
    long long row = blockIdx.x;
    float* p = attn + row * (long long)N_;
    __half* ph = probs + row * (long long)N_;
    int t = threadIdx.x;
    float v[8];
    float mx = -INFINITY;
#pragma unroll
    for (int i = 0; i < 8; i++) { v[i] = p[t + i * 256]; mx = fmaxf(mx, v[i]); }
    mx = blockReduceMax(mx, sh);
    float s = 0.0f;
#pragma unroll
    for (int i = 0; i < 8; i++) { v[i] = __expf(v[i] - mx); s += v[i]; }
    s = blockReduceSum(s, sh);
    float inv = 1.0f / s;
#pragma unroll
    for (int i = 0; i < 8; i++) {
        int c = t + i * 256;
        float w = v[i] * inv;
        p[c] = w;
        ph[c] = __float2half_rn(w);
    }
}

// ---------------- fp32 -> fp16 round ----------------
__global__ __launch_bounds__(256)
void round_kernel(const float* __restrict__ src, __half* __restrict__ hi, long long n) {
    long long i = ((long long)blockIdx.x * 256 + threadIdx.x) * 4;
    if (i >= n) return;
    float4 v = *(const float4*)(src + i);
    __half h[4] = {__float2half_rn(v.x), __float2half_rn(v.y),
                   __float2half_rn(v.z), __float2half_rn(v.w)};
    *(uint2*)(hi + i) = *(uint2*)h;
}

// ---------------- epilogue ids ----------------
enum { EPI_NONE = 0, EPI_BIAS_GELU = 1, EPI_BIAS_RES = 2, EPI_SCORE = 3 };

static constexpr int STAGES = 4;

// ============================================================================
// WMMA fp16 GEMM (ABT): C[M,Nc] = A[M,K] @ B[Nc,K]^T
// 128x128 block, 4 warps (64x64 warp tile, 2x2), K-chunk 32,
// 4-stage cp.async ring, one __syncthreads per chunk.
// Rationale: 64x64 warp tiles cut per-chunk smem fragment traffic 48KB->32KB.
// ============================================================================
static constexpr int S1_A = 0, S1_B = 5120;
static constexpr int S1_STAGE = 10240;                       // elements per stage
static constexpr int S1_SMEM  = STAGES * S1_STAGE * 2;       // 81920 B (>= 67584 epi)

template <int EPI, int OSPLIT>
__global__ __launch_bounds__(128, 2)
void wgemm_abt(const __half* __restrict__ A, const __half* __restrict__ Bm,
               float* __restrict__ Cf, __half* __restrict__ Ch,
               int K, int lda, int ldb, int ldc,
               long long aOut, long long aIn, long long bOut, long long bIn,
               long long cOut, long long cIn, int Hdiv,
               const float* __restrict__ bias, const float* __restrict__ resid,
               float scale, const int* __restrict__ mask, int maskld) {
    extern __shared__ char smem_raw[];
    __half* sm = (__half*)smem_raw;

    int z = blockIdx.z, zb = z / Hdiv, zh = z % Hdiv;
    A  += (long long)zb * aOut + (long long)zh * aIn;
    Bm += (long long)zb * bOut + (long long)zh * bIn;
    long long cz = (long long)zb * cOut + (long long)zh * cIn;
    int m0 = blockIdx.y * 128, n0 = blockIdx.x * 128;

    int t = threadIdx.x, wid = t >> 5;
    int warpM = wid >> 1, warpN = wid & 1;     // 2x2 warps, 64x64 each

    // loads: thread t covers row t of A (cols 0..31) and row t of B (cols 0..31)
    const __half* gA = A  + (long long)(m0 + t) * lda;
    const __half* gB = Bm + (long long)(n0 + t) * ldb;
    int aoff = t * 40;
    int boff = t * 40;

    wmma::fragment<wmma::accumulator, 16, 16, 16, float> acc[4][4];
#pragma unroll
    for (int i = 0; i < 4; i++)
#pragma unroll
        for (int j = 0; j < 4; j++) wmma::fill_fragment(acc[i][j], 0.0f);

    const int NC = K >> 5;

    auto stage_copy = [&](int ch) {
        __half* s = sm + (ch % STAGES) * S1_STAGE;
        int kc = ch << 5;
#pragma unroll
        for (int seg = 0; seg < 4; seg++) {
            cp16(s + S1_A + aoff + seg * 8, gA + kc + seg * 8);
            cp16(s + S1_B + boff + seg * 8, gB + kc + seg * 8);
        }
    };

#pragma unroll
    for (int sfill = 0; sfill < STAGES - 1; sfill++) {
        if (sfill < NC) stage_copy(sfill);
        cp_commit();
    }

    for (int ch = 0; ch < NC; ch++) {
        cp_wait<STAGES - 2>();
        __syncthreads();
        int nx = ch + STAGES - 1;
        if (nx < NC) stage_copy(nx);
        cp_commit();

        const __half* s = sm + (ch % STAGES) * S1_STAGE;
#pragma unroll
        for (int ks = 0; ks < 2; ks++) {
            wmma::fragment<wmma::matrix_a, 16, 16, 16, __half, wmma::row_major> fa[4];
#pragma unroll
            for (int mi = 0; mi < 4; mi++)
                wmma::load_matrix_sync(fa[mi], s + S1_A + (warpM * 64 + mi * 16) * 40 + ks * 16, 40);
#pragma unroll
            for (int ni = 0; ni < 4; ni++) {
                wmma::fragment<wmma::matrix_b, 16, 16, 16, __half, wmma::col_major> fb;
                wmma::load_matrix_sync(fb, s + S1_B + (warpN * 64 + ni * 16) * 40 + ks * 16, 40);
#pragma unroll
                for (int mi = 0; mi < 4; mi++)
                    wmma::mma_sync(acc[mi][ni], fa[mi], fb, acc[mi][ni]);
            }
        }
    }

    // epilogue via smem (fp32, ldm=132); sync first: smem aliases stage buffers
    __syncthreads();
    float* smc = (float*)smem_raw;
#pragma unroll
    for (int mi = 0; mi < 4; mi++)
#pragma unroll
        for (int ni = 0; ni < 4; ni++)
            wmma::store_matrix_sync(&smc[(warpM * 64 + mi * 16) * 132 + warpN * 64 + ni * 16],
                                    acc[mi][ni], 132, wmma::mem_row_major);
    __syncthreads();

    int r  = t;                           // row 0..127
    int mg = m0 + r;
    long long cbase = cz + (long long)mg * ldc + n0;
    const int* mrow = (EPI == EPI_SCORE) ? mask + (long long)zb * maskld : nullptr;

#pragma unroll
    for (int j4 = 0; j4 < 128; j4 += 4) {
        float v[4];
#pragma unroll
        for (int q = 0; q < 4; q++) v[q] = smc[r * 132 + j4 + q];
        if (EPI == EPI_SCORE) {
            int4 mv = *(const int4*)&mrow[n0 + j4];
            int mm[4] = {mv.x, mv.y, mv.z, mv.w};
#pragma unroll
            for (int q = 0; q < 4; q++) {
                v[q] *= scale;
                if (mm[q] == 0) v[q] = -INFINITY;
            }
        } else if (EPI == EPI_BIAS_GELU) {
            float4 bv = *(const float4*)&bias[n0 + j4];
            float bb[4] = {bv.x, bv.y, bv.z, bv.w};
#pragma unroll
            for (int q = 0; q < 4; q++) {
                float xv = v[q] + bb[q];
                v[q] = 0.5f * xv * (1.0f + erff(xv * 0.70710678118654752f));
            }
        } else if (EPI == EPI_BIAS_RES) {
            float4 bv = *(const float4*)&bias[n0 + j4];
            float4 rv = *(const float4*)&resid[cbase + j4];
            v[0] += bv.x + rv.x; v[1] += bv.y + rv.y;
            v[2] += bv.z + rv.z; v[3] += bv.w + rv.w;
        }
        if (OSPLIT) {
            __half hv[4];
#pragma unroll
            for (int q = 0; q < 4; q++) hv[q] = __float2half_rn(v[q]);
            *(uint2*)(Ch + cbase + j4) = *(uint2*)hv;
        } else {
            *(float4*)&Cf[cbase + j4] = make_float4(v[0], v[1], v[2], v[3]);
        }
    }
}

// ============================================================================
// WMMA fp16 GEMM (AB, Nc=64): C[M,64] = A[M,K] @ B[K,64]
// 128x64 block, 8 warps (32x32 warp tile), K-chunk 32, 4-stage ring. (unchanged)
// ============================================================================
static constexpr int S2_A = 0, S2_B = 5120;   // B tile 32x72
static constexpr int S2_STAGE = 7424;
static constexpr int S2_SMEM  = STAGES * S2_STAGE * 2;   // 59392 B (>= 34816 epi)

__global__ __launch_bounds__(256, 2)
void wgemm_ab64(const __half* __restrict__ A, const __half* __restrict__ Bm,
                __half* __restrict__ Ch,
                int K, int lda, int ldb, int ldc,
                long long aOut, long long aIn, long long bOut, long long bIn,
                long long cOut, long long cIn, int Hdiv) {
    extern __shared__ char smem_raw[];
    __half* sm = (__half*)smem_raw;

    int z = blockIdx.z, zb = z / Hdiv, zh = z % Hdiv;
    A  += (long long)zb * aOut + (long long)zh * aIn;
    Bm += (long long)zb * bOut + (long long)zh * bIn;
    long long cz = (long long)zb * cOut + (long long)zh * cIn;
    int m0 = blockIdx.y * 128;

    int t = threadIdx.x, wid = t >> 5;
    int warpM = wid & 3, warpN = wid >> 2;

    int lrow = t >> 1, lcol = (t & 1) * 16;
    const __half* gA = A + (long long)(m0 + lrow) * lda + lcol;
    int aoff = lrow * 40 + lcol;
    int brow = t >> 3, bcol = (t & 7) * 8;
    const __half* gB = Bm + (long long)brow * ldb + bcol;
    int boff = brow * 72 + bcol;

    wmma::fragment<wmma::accumulator, 16, 16, 16, float> acc[2][2];
#pragma unroll
    for (int i = 0; i < 2; i++)
#pragma unroll
        for (int j = 0; j < 2; j++) wmma::fill_fragment(acc[i][j], 0.0f);

    const int NC = K >> 5;

    auto stage_copy = [&](int ch) {
        __half* s = sm + (ch % STAGES) * S2_STAGE;
        int kc = ch << 5;
        cp16(s + S2_A + aoff, gA + kc); cp16(s + S2_A + aoff + 8, gA + kc + 8);
        cp16(s + S2_B + boff, gB + (long long)kc * ldb);
    };

#pragma unroll
    for (int sfill = 0; sfill < STAGES - 1; sfill++) {
        if (sfill < NC) stage_copy(sfill);
        cp_commit();
    }

    for (int ch = 0; ch < NC; ch++) {
        cp_wait<STAGES - 2>();
        __syncthreads();
        int nx = ch + STAGES - 1;
        if (nx < NC) stage_copy(nx);
        cp_commit();

        const __half* s = sm + (ch % STAGES) * S2_STAGE;
#pragma unroll
        for (int ks = 0; ks < 2; ks++) {
            wmma::fragment<wmma::matrix_a, 16, 16, 16, __half, wmma::row_major> fa[2];
#pragma unroll
            for (int mi = 0; mi < 2; mi++)
                wmma::load_matrix_sync(fa[mi], s + S2_A + (warpM * 32 + mi * 16) * 40 + ks * 16, 40);
#pragma unroll
            for (int ni = 0; ni < 2; ni++) {
                wmma::fragment<wmma::matrix_b, 16, 16, 16, __half, wmma::row_major> fb;
                wmma::load_matrix_sync(fb, s + S2_B + ks * 16 * 72 + warpN * 32 + ni * 16, 72);
#pragma unroll
                for (int mi = 0; mi < 2; mi++)
                    wmma::mma_sync(acc[mi][ni], fa[mi], fb, acc[mi][ni]);
            }
        }
    }

    __syncthreads();
    float* smc = (float*)smem_raw;
#pragma unroll
    for (int mi = 0; mi < 2; mi++)
#pragma unroll
        for (int ni = 0; ni < 2; ni++)
            wmma::store_matrix_sync(&smc[(warpM * 32 + mi * 16) * 68 + warpN * 32 + ni * 16],
                                    acc[mi][ni], 68, wmma::mem_row_major);
    __syncthreads();

    int r  = t >> 1;
    int c0 = (t & 1) * 32;
    long long cbase = cz + (long long)(m0 + r) * ldc + c0;
#pragma unroll
    for (int j4 = 0; j4 < 32; j4 += 4) {
        __half hv[4];
#pragma unroll
        for (int q = 0; q < 4; q++) hv[q] = __float2half_rn(smc[r * 68 + c0 + j4 + q]);
        *(uint2*)(Ch + cbase + j4) = *(uint2*)hv;
    }
}

// ---------------- launch ----------------
extern "C" void kernel_launch(void* const* d_in, const int* in_sizes, int n_in,
                              void* d_out, int out_size) {
    const float* x      = (const float*)d_in[0];
    const int*   mask   = (const int*)  d_in[1];
    const float* qkv_w  = (const float*)d_in[2];
    const float* proj_w = (const float*)d_in[3];
    const float* proj_b = (const float*)d_in[4];
    const float* ln1_g  = (const float*)d_in[5];
    const float* ln1_b  = (const float*)d_in[6];
    const float* ln2_g  = (const float*)d_in[7];
    const float* ln2_b  = (const float*)d_in[8];
    const float* fc1_w  = (const float*)d_in[9];
    const float* fc1_b  = (const float*)d_in[10];
    const float* fc2_w  = (const float*)d_in[11];
    const float* fc2_b  = (const float*)d_in[12];

    float* out_x = (float*)d_out;

#define GA(sym, var) float* var; cudaGetSymbolAddress((void**)&var, sym)
#define GH(sym, var) __half* var; cudaGetSymbolAddress((void**)&var, sym)
    GA(g_x1, x1); GA(g_attn_fallback, attn_fb);
    GH(g_xn, xn);   GH(g_qkv, qkv); GH(g_ctx, ctx);
    GH(g_hn, hn);   GH(g_ff, ff);   GH(g_ap, ap);
    GH(g_wqkv, wqkv); GH(g_wproj, wproj);
    GH(g_wfc1, wfc1); GH(g_wfc2, wfc2);
#undef GA
#undef GH

    float* attn = ((long long)out_size >= XSZ + ATTNSZ) ? (out_x + XSZ) : attn_fb;

    cudaFuncSetAttribute(wgemm_abt<EPI_NONE, 1>,      cudaFuncAttributeMaxDynamicSharedMemorySize, S1_SMEM);
    cudaFuncSetAttribute(wgemm_abt<EPI_SCORE, 0>,     cudaFuncAttributeMaxDynamicSharedMemorySize, S1_SMEM);
    cudaFuncSetAttribute(wgemm_abt<EPI_BIAS_RES, 0>,  cudaFuncAttributeMaxDynamicSharedMemorySize, S1_SMEM);
    cudaFuncSetAttribute(wgemm_abt<EPI_BIAS_GELU, 1>, cudaFuncAttributeMaxDynamicSharedMemorySize, S1_SMEM);
    cudaFuncSetAttribute(wgemm_ab64,                  cudaFuncAttributeMaxDynamicSharedMemorySize, S2_SMEM);

    const float scale = 0.125f;

    auto roundw = [](const float* s, __half* h, long long n) {
        round_kernel<<<(unsigned)((n / 4 + 255) / 256), 256>>>(s, h, n);
    };

    roundw(qkv_w,  wqkv,  (long long)3 * C_ * C_);
    roundw(proj_w, wproj, (long long)C_ * C_);
    roundw(fc1_w,  wfc1,  (long long)DFF * C_);
    roundw(fc2_w,  wfc2,  (long long)C_ * DFF);

    // 1) ln1 -> fp16
    ln_h_kernel<<<M_, 256>>>(x, ln1_g, ln1_b, xn);

    // 2) qkv = xn @ qkv_w^T  (fp16 output)
    wgemm_abt<EPI_NONE, 1><<<dim3(3 * C_ / 128, M_ / 128, 1), 128, S1_SMEM>>>(
        xn, wqkv, nullptr, qkv, C_, C_, C_, 3 * C_,
        0, 0, 0, 0, 0, 0, 1, nullptr, nullptr, 0.f, nullptr, 0);

    // 3) scores = scale * q @ k^T, masked -> fp32 attn
    wgemm_abt<EPI_SCORE, 0><<<dim3(N_ / 128, N_ / 128, B_ * H_), 128, S1_SMEM>>>(
        qkv, qkv + C_, attn, nullptr, D_, 3 * C_, 3 * C_, N_,
        (long long)N_ * 3 * C_, D_,
        (long long)N_ * 3 * C_, D_,
        (long long)H_ * N_ * N_, (long long)N_ * N_,
        H_, nullptr, nullptr, scale, mask, N_);

    // 4) softmax -> fp32 out + fp16 probs
    softmax_h_kernel<<<B_ * H_ * N_, 256>>>(attn, ap);

    // 5) ctx = attn @ v  (fp16)
    wgemm_ab64<<<dim3(1, N_ / 128, B_ * H_), 256, S2_SMEM>>>(
        ap, qkv + 2 * C_, ctx,
        N_, N_, 3 * C_, C_,
        (long long)H_ * N_ * N_, (long long)N_ * N_,
        (long long)N_ * 3 * C_, D_,
        (long long)N_ * C_, D_,
        H_);

    // 6) x1 = x + ctx @ proj_w^T + proj_b  (fp32)
    wgemm_abt<EPI_BIAS_RES, 0><<<dim3(C_ / 128, M_ / 128, 1), 128, S1_SMEM>>>(
        ctx, wproj, x1, nullptr, C_, C_, C_, C_,
        0, 0, 0, 0, 0, 0, 1, proj_b, x, 0.f, nullptr, 0);

    // 7) ln2 -> fp16
    ln_h_kernel<<<M_, 256>>>(x1, ln2_g, ln2_b, hn);

    // 8) ff = gelu(hn @ fc1_w^T + fc1_b)  (fp16)
    wgemm_abt<EPI_BIAS_GELU, 1><<<dim3(DFF / 128, M_ / 128, 1), 128, S1_SMEM>>>(
        hn, wfc1, nullptr, ff, C_, C_, C_, DFF,
        0, 0, 0, 0, 0, 0, 1, fc1_b, nullptr, 0.f, nullptr, 0);

    // 9) out_x = x1 + ff @ fc2_w^T + fc2_b  (fp32)
    wgemm_abt<EPI_BIAS_RES, 0><<<dim3(C_ / 128, M_ / 128, 1), 128, S1_SMEM>>>(
        ff, wfc2, out_x, nullptr, DFF, DFF, DFF, C_,
        0, 0, 0, 0, 0, 0, 1, fc2_b, x1, 0.f, nullptr, 0);
}

// round 17
// speedup vs baseline: 1.1093x; 1.1093x over previous
#include <cuda_runtime.h>
#include <cuda_fp16.h>
#include <mma.h>
#include <cstdint>
#include <math.h>

using namespace nvcuda;

// Problem constants
static constexpr int B_  = 2;
static constexpr int N_  = 2048;
static constexpr int C_  = 1024;
static constexpr int H_  = 16;
static constexpr int D_  = 64;
static constexpr int DFF = 4096;
static constexpr int M_  = B_ * N_;
static constexpr long long XSZ   = (long long)B_ * N_ * C_;
static constexpr long long ATTNSZ= (long long)B_ * H_ * N_ * N_;

// ---------------- scratch (device globals) ----------------
__device__ __align__(256) float g_x1 [M_ * C_];
__device__ __align__(256) float g_attn_fallback[ATTNSZ];
__device__ __align__(256) __half g_xn [M_ * C_];
__device__ __align__(256) __half g_qkv[M_ * 3 * C_];
__device__ __align__(256) __half g_ctx[M_ * C_];
__device__ __align__(256) __half g_hn [M_ * C_];
__device__ __align__(256) __half g_ff [M_ * DFF];
__device__ __align__(256) __half g_ap [ATTNSZ];      // fp16 scores, then probs (in place)
__device__ __align__(256) __half g_wqkv[3 * C_ * C_];
__device__ __align__(256) __half g_wproj[C_ * C_];
__device__ __align__(256) __half g_wfc1[DFF * C_];
__device__ __align__(256) __half g_wfc2[C_ * DFF];

// ---------------- cp.async helpers ----------------
__device__ __forceinline__ void cp16(void* sdst, const void* gsrc) {
    uint32_t s = (uint32_t)__cvta_generic_to_shared(sdst);
    asm volatile("cp.async.cg.shared.global [%0], [%1], 16;" :: "r"(s), "l"(gsrc));
}
__device__ __forceinline__ void cp_commit() {
    asm volatile("cp.async.commit_group;" ::: "memory");
}
template <int N>
__device__ __forceinline__ void cp_wait() {
    asm volatile("cp.async.wait_group %0;" :: "n"(N) : "memory");
}

// ---------------- block reductions ----------------
__device__ __forceinline__ float blockReduceSum(float val, float* shbuf) {
    int lane = threadIdx.x & 31, wid = threadIdx.x >> 5;
#pragma unroll
    for (int o = 16; o > 0; o >>= 1) val += __shfl_xor_sync(0xffffffffu, val, o);
    if (lane == 0) shbuf[wid] = val;
    __syncthreads();
    if (wid == 0) {
        val = (lane < 8) ? shbuf[lane] : 0.0f;
#pragma unroll
        for (int o = 4; o > 0; o >>= 1) val += __shfl_xor_sync(0xffffffffu, val, o);
        if (lane == 0) shbuf[0] = val;
    }
    __syncthreads();
    float r = shbuf[0];
    __syncthreads();
    return r;
}
__device__ __forceinline__ float blockReduceMax(float val, float* shbuf) {
    int lane = threadIdx.x & 31, wid = threadIdx.x >> 5;
#pragma unroll
    for (int o = 16; o > 0; o >>= 1) val = fmaxf(val, __shfl_xor_sync(0xffffffffu, val, o));
    if (lane == 0) shbuf[wid] = val;
    __syncthreads();
    if (wid == 0) {
        val = (lane < 8) ? shbuf[lane] : -INFINITY;
#pragma unroll
        for (int o = 4; o > 0; o >>= 1) val = fmaxf(val, __shfl_xor_sync(0xffffffffu, val, o));
        if (lane == 0) shbuf[0] = val;
    }
    __syncthreads();
    float r = shbuf[0];
    __syncthreads();
    return r;
}

// ---------------- layernorm -> fp16 ----------------
__global__ __launch_bounds__(256)
void ln_h_kernel(const float* __restrict__ x, const float* __restrict__ g,
                 const float* __restrict__ b, __half* __restrict__ out) {
    __shared__ float sh[8];
    long long row = blockIdx.x;
    const float* xr = x + row * C_;
    int t = threadIdx.x;
    float v[4];
    float s = 0.0f;
#pragma unroll
    for (int i = 0; i < 4; i++) { v[i] = xr[t + i * 256]; s += v[i]; }
    s = blockReduceSum(s, sh);
    float mu = s * (1.0f / C_);
    float var = 0.0f;
#pragma unroll
    for (int i = 0; i < 4; i++) { float d = v[i] - mu; var += d * d; }
    var = blockReduceSum(var, sh);
    float r = rsqrtf(var * (1.0f / C_) + 1e-5f);
#pragma unroll
    for (int i = 0; i < 4; i++) {
        int c = t + i * 256;
        out[row * C_ + c] = __float2half_rn((v[i] - mu) * r * g[c] + b[c]);
    }
}

// ---------------- softmax: fp16 scores in -> fp32 attn out + fp16 probs in place ----
__global__ __launch_bounds__(256)
void softmax_hh_kernel(__half* __restrict__ sp, float* __restrict__ attn) {
    __shared__ float sh[8];
    long long row = blockIdx.x;
    __half* ph = sp + row * (long long)N_;
    float* p = attn + row * (long long)N_;
    int t = threadIdx.x;
    float v[8];
    float mx = -INFINITY;
#pragma unroll
    for (int i = 0; i < 8; i++) { v[i] = __half2float(ph[t + i * 256]); mx = fmaxf(mx, v[i]); }
    mx = blockReduceMax(mx, sh);
    float s = 0.0f;
#pragma unroll
    for (int i = 0; i < 8; i++) { v[i] = __expf(v[i] - mx); s += v[i]; }
    s = blockReduceSum(s, sh);
    float inv = 1.0f / s;
#pragma unroll
    for (int i = 0; i < 8; i++) {
        int c = t + i * 256;
        float w = v[i] * inv;
        p[c] = w;
        ph[c] = __float2half_rn(w);
    }
}

// ---------------- fp32 -> fp16 round ----------------
__global__ __launch_bounds__(256)
void round_kernel(const float* __restrict__ src, __half* __restrict__ hi, long long n) {
    long long i = ((long long)blockIdx.x * 256 + threadIdx.x) * 4;
    if (i >= n) return;
    float4 v = *(const float4*)(src + i);
    __half h[4] = {__float2half_rn(v.x), __float2half_rn(v.y),
                   __float2half_rn(v.z), __float2half_rn(v.w)};
    *(uint2*)(hi + i) = *(uint2*)h;
}

// ---------------- epilogue ids ----------------
enum { EPI_NONE = 0, EPI_BIAS_GELU = 1, EPI_BIAS_RES = 2, EPI_SCORE = 3 };

static constexpr int STAGES = 4;

// ============================================================================
// WMMA fp16 GEMM (ABT): C[M,Nc] = A[M,K] @ B[Nc,K]^T
// 128x128 block, 8 warps (32x64 warp tile), K-chunk 32,
// 4-stage cp.async ring, one __syncthreads per chunk.  (R15-proven config)
// ============================================================================
static constexpr int S1_A = 0, S1_B = 5120;
static constexpr int S1_STAGE = 10240;                       // elements per stage
static constexpr int S1_SMEM  = STAGES * S1_STAGE * 2;       // 81920 B (>= 67584 epi)

template <int EPI, int OSPLIT>
__global__ __launch_bounds__(256, 2)
void wgemm_abt(const __half* __restrict__ A, const __half* __restrict__ Bm,
               float* __restrict__ Cf, __half* __restrict__ Ch,
               int K, int lda, int ldb, int ldc,
               long long aOut, long long aIn, long long bOut, long long bIn,
               long long cOut, long long cIn, int Hdiv,
               const float* __restrict__ bias, const float* __restrict__ resid,
               float scale, const int* __restrict__ mask, int maskld) {
    extern __shared__ char smem_raw[];
    __half* sm = (__half*)smem_raw;

    int z = blockIdx.z, zb = z / Hdiv, zh = z % Hdiv;
    A  += (long long)zb * aOut + (long long)zh * aIn;
    Bm += (long long)zb * bOut + (long long)zh * bIn;
    long long cz = (long long)zb * cOut + (long long)zh * cIn;
    int m0 = blockIdx.y * 128, n0 = blockIdx.x * 128;

    int t = threadIdx.x, wid = t >> 5;
    int warpM = wid & 3, warpN = wid >> 2;

    int lrow = t >> 1, lcol = (t & 1) * 16;
    const __half* gA = A  + (long long)(m0 + lrow) * lda + lcol;
    const __half* gB = Bm + (long long)(n0 + lrow) * ldb + lcol;
    int soff = lrow * 40 + lcol;

    wmma::fragment<wmma::accumulator, 16, 16, 16, float> acc[2][4];
#pragma unroll
    for (int i = 0; i < 2; i++)
#pragma unroll
        for (int j = 0; j < 4; j++) wmma::fill_fragment(acc[i][j], 0.0f);

    const int NC = K >> 5;

    auto stage_copy = [&](int ch) {
        __half* s = sm + (ch % STAGES) * S1_STAGE;
        int kc = ch << 5;
        cp16(s + S1_A + soff, gA + kc); cp16(s + S1_A + soff + 8, gA + kc + 8);
        cp16(s + S1_B + soff, gB + kc); cp16(s + S1_B + soff + 8, gB + kc + 8);
    };

#pragma unroll
    for (int sfill = 0; sfill < STAGES - 1; sfill++) {
        if (sfill < NC) stage_copy(sfill);
        cp_commit();
    }

    for (int ch = 0; ch < NC; ch++) {
        cp_wait<STAGES - 2>();
        __syncthreads();
        int nx = ch + STAGES - 1;
        if (nx < NC) stage_copy(nx);
        cp_commit();

        const __half* s = sm + (ch % STAGES) * S1_STAGE;
#pragma unroll
        for (int ks = 0; ks < 2; ks++) {
            wmma::fragment<wmma::matrix_a, 16, 16, 16, __half, wmma::row_major> fa[2];
#pragma unroll
            for (int mi = 0; mi < 2; mi++)
                wmma::load_matrix_sync(fa[mi], s + S1_A + (warpM * 32 + mi * 16) * 40 + ks * 16, 40);
#pragma unroll
            for (int ni = 0; ni < 4; ni++) {
                wmma::fragment<wmma::matrix_b, 16, 16, 16, __half, wmma::col_major> fb;
                wmma::load_matrix_sync(fb, s + S1_B + (warpN * 64 + ni * 16) * 40 + ks * 16, 40);
#pragma unroll
                for (int mi = 0; mi < 2; mi++)
                    wmma::mma_sync(acc[mi][ni], fa[mi], fb, acc[mi][ni]);
            }
        }
    }

    // epilogue via smem (fp32, ldm=132); sync first: smem aliases stage buffers
    __syncthreads();
    float* smc = (float*)smem_raw;
#pragma unroll
    for (int mi = 0; mi < 2; mi++)
#pragma unroll
        for (int ni = 0; ni < 4; ni++)
            wmma::store_matrix_sync(&smc[(warpM * 32 + mi * 16) * 132 + warpN * 64 + ni * 16],
                                    acc[mi][ni], 132, wmma::mem_row_major);
    __syncthreads();

    int r  = t >> 1;
    int c0 = (t & 1) * 64;
    int mg = m0 + r;
    long long cbase = cz + (long long)mg * ldc + n0 + c0;
    const int* mrow = (EPI == EPI_SCORE) ? mask + (long long)zb * maskld : nullptr;

#pragma unroll
    for (int j4 = 0; j4 < 64; j4 += 4) {
        float v[4];
#pragma unroll
        for (int q = 0; q < 4; q++) v[q] = smc[r * 132 + c0 + j4 + q];
        if (EPI == EPI_SCORE) {
            int4 mv = *(const int4*)&mrow[n0 + c0 + j4];
            int mm[4] = {mv.x, mv.y, mv.z, mv.w};
#pragma unroll
            for (int q = 0; q < 4; q++) {
                v[q] *= scale;
                if (mm[q] == 0) v[q] = -INFINITY;
            }
        } else if (EPI == EPI_BIAS_GELU) {
            float4 bv = *(const float4*)&bias[n0 + c0 + j4];
            float bb[4] = {bv.x, bv.y, bv.z, bv.w};
#pragma unroll
            for (int q = 0; q < 4; q++) {
                float xv = v[q] + bb[q];
                v[q] = 0.5f * xv * (1.0f + erff(xv * 0.70710678118654752f));
            }
        } else if (EPI == EPI_BIAS_RES) {
            float4 bv = *(const float4*)&bias[n0 + c0 + j4];
            float4 rv = *(const float4*)&resid[cbase + j4];
            v[0] += bv.x + rv.x; v[1] += bv.y + rv.y;
            v[2] += bv.z + rv.z; v[3] += bv.w + rv.w;
        }
        if (OSPLIT) {
            __half hv[4];
#pragma unroll
            for (int q = 0; q < 4; q++) hv[q] = __float2half_rn(v[q]);
            *(uint2*)(Ch + cbase + j4) = *(uint2*)hv;
        } else {
            *(float4*)&Cf[cbase + j4] = make_float4(v[0], v[1], v[2], v[3]);
        }
    }
}

// ============================================================================
// WMMA fp16 GEMM (AB, Nc=64): C[M,64] = A[M,K] @ B[K,64]
// 128x64 block, 8 warps (32x32 warp tile), K-chunk 32, 4-stage ring.
// ============================================================================
static constexpr int S2_A = 0, S2_B = 5120;   // B tile 32x72
static constexpr int S2_STAGE = 7424;
static constexpr int S2_SMEM  = STAGES * S2_STAGE * 2;   // 59392 B (>= 34816 epi)

__global__ __launch_bounds__(256, 2)
void wgemm_ab64(const __half* __restrict__ A, const __half* __restrict__ Bm,
                __half* __restrict__ Ch,
                int K, int lda, int ldb, int ldc,
                long long aOut, long long aIn, long long bOut, long long bIn,
                long long cOut, long long cIn, int Hdiv) {
    extern __shared__ char smem_raw[];
    __half* sm = (__half*)smem_raw;

    int z = blockIdx.z, zb = z / Hdiv, zh = z % Hdiv;
    A  += (long long)zb * aOut + (long long)zh * aIn;
    Bm += (long long)zb * bOut + (long long)zh * bIn;
    long long cz = (long long)zb * cOut + (long long)zh * cIn;
    int m0 = blockIdx.y * 128;

    int t = threadIdx.x, wid = t >> 5;
    int warpM = wid & 3, warpN = wid >> 2;

    int lrow = t >> 1, lcol = (t & 1) * 16;
    const __half* gA = A + (long long)(m0 + lrow) * lda + lcol;
    int aoff = lrow * 40 + lcol;
    int brow = t >> 3, bcol = (t & 7) * 8;
    const __half* gB = Bm + (long long)brow * ldb + bcol;
    int boff = brow * 72 + bcol;

    wmma::fragment<wmma::accumulator, 16, 16, 16, float> acc[2][2];
#pragma unroll
    for (int i = 0; i < 2; i++)
#pragma unroll
        for (int j = 0; j < 2; j++) wmma::fill_fragment(acc[i][j], 0.0f);

    const int NC = K >> 5;

    auto stage_copy = [&](int ch) {
        __half* s = sm + (ch % STAGES) * S2_STAGE;
        int kc = ch << 5;
        cp16(s + S2_A + aoff, gA + kc); cp16(s + S2_A + aoff + 8, gA + kc + 8);
        cp16(s + S2_B + boff, gB + (long long)kc * ldb);
    };

#pragma unroll
    for (int sfill = 0; sfill < STAGES - 1; sfill++) {
        if (sfill < NC) stage_copy(sfill);
        cp_commit();
    }

    for (int ch = 0; ch < NC; ch++) {
        cp_wait<STAGES - 2>();
        __syncthreads();
        int nx = ch + STAGES - 1;
        if (nx < NC) stage_copy(nx);
        cp_commit();

        const __half* s = sm + (ch % STAGES) * S2_STAGE;
#pragma unroll
        for (int ks = 0; ks < 2; ks++) {
            wmma::fragment<wmma::matrix_a, 16, 16, 16, __half, wmma::row_major> fa[2];
#pragma unroll
            for (int mi = 0; mi < 2; mi++)
                wmma::load_matrix_sync(fa[mi], s + S2_A + (warpM * 32 + mi * 16) * 40 + ks * 16, 40);
#pragma unroll
            for (int ni = 0; ni < 2; ni++) {
                wmma::fragment<wmma::matrix_b, 16, 16, 16, __half, wmma::row_major> fb;
                wmma::load_matrix_sync(fb, s + S2_B + ks * 16 * 72 + warpN * 32 + ni * 16, 72);
#pragma unroll
                for (int mi = 0; mi < 2; mi++)
                    wmma::mma_sync(acc[mi][ni], fa[mi], fb, acc[mi][ni]);
            }
        }
    }

    __syncthreads();
    float* smc = (float*)smem_raw;
#pragma unroll
    for (int mi = 0; mi < 2; mi++)
#pragma unroll
        for (int ni = 0; ni < 2; ni++)
            wmma::store_matrix_sync(&smc[(warpM * 32 + mi * 16) * 68 + warpN * 32 + ni * 16],
                                    acc[mi][ni], 68, wmma::mem_row_major);
    __syncthreads();

    int r  = t >> 1;
    int c0 = (t & 1) * 32;
    long long cbase = cz + (long long)(m0 + r) * ldc + c0;
#pragma unroll
    for (int j4 = 0; j4 < 32; j4 += 4) {
        __half hv[4];
#pragma unroll
        for (int q = 0; q < 4; q++) hv[q] = __float2half_rn(smc[r * 68 + c0 + j4 + q]);
        *(uint2*)(Ch + cbase + j4) = *(uint2*)hv;
    }
}

// ---------------- launch ----------------
extern "C" void kernel_launch(void* const* d_in, const int* in_sizes, int n_in,
                              void* d_out, int out_size) {
    const float* x      = (const float*)d_in[0];
    const int*   mask   = (const int*)  d_in[1];
    const float* qkv_w  = (const float*)d_in[2];
    const float* proj_w = (const float*)d_in[3];
    const float* proj_b = (const float*)d_in[4];
    const float* ln1_g  = (const float*)d_in[5];
    const float* ln1_b  = (const float*)d_in[6];
    const float* ln2_g  = (const float*)d_in[7];
    const float* ln2_b  = (const float*)d_in[8];
    const float* fc1_w  = (const float*)d_in[9];
    const float* fc1_b  = (const float*)d_in[10];
    const float* fc2_w  = (const float*)d_in[11];
    const float* fc2_b  = (const float*)d_in[12];

    float* out_x = (float*)d_out;

#define GA(sym, var) float* var; cudaGetSymbolAddress((void**)&var, sym)
#define GH(sym, var) __half* var; cudaGetSymbolAddress((void**)&var, sym)
    GA(g_x1, x1); GA(g_attn_fallback, attn_fb);
    GH(g_xn, xn);   GH(g_qkv, qkv); GH(g_ctx, ctx);
    GH(g_hn, hn);   GH(g_ff, ff);   GH(g_ap, ap);
    GH(g_wqkv, wqkv); GH(g_wproj, wproj);
    GH(g_wfc1, wfc1); GH(g_wfc2, wfc2);
#undef GA
#undef GH

    float* attn = ((long long)out_size >= XSZ + ATTNSZ) ? (out_x + XSZ) : attn_fb;

    cudaFuncSetAttribute(wgemm_abt<EPI_NONE, 1>,      cudaFuncAttributeMaxDynamicSharedMemorySize, S1_SMEM);
    cudaFuncSetAttribute(wgemm_abt<EPI_SCORE, 1>,     cudaFuncAttributeMaxDynamicSharedMemorySize, S1_SMEM);
    cudaFuncSetAttribute(wgemm_abt<EPI_BIAS_RES, 0>,  cudaFuncAttributeMaxDynamicSharedMemorySize, S1_SMEM);
    cudaFuncSetAttribute(wgemm_abt<EPI_BIAS_GELU, 1>, cudaFuncAttributeMaxDynamicSharedMemorySize, S1_SMEM);
    cudaFuncSetAttribute(wgemm_ab64,                  cudaFuncAttributeMaxDynamicSharedMemorySize, S2_SMEM);

    const float scale = 0.125f;

    auto roundw = [](const float* s, __half* h, long long n) {
        round_kernel<<<(unsigned)((n / 4 + 255) / 256), 256>>>(s, h, n);
    };

    roundw(qkv_w,  wqkv,  (long long)3 * C_ * C_);
    roundw(proj_w, wproj, (long long)C_ * C_);
    roundw(fc1_w,  wfc1,  (long long)DFF * C_);
    roundw(fc2_w,  wfc2,  (long long)C_ * DFF);

    // 1) ln1 -> fp16
    ln_h_kernel<<<M_, 256>>>(x, ln1_g, ln1_b, xn);

    // 2) qkv = xn @ qkv_w^T  (fp16 output)
    wgemm_abt<EPI_NONE, 1><<<dim3(3 * C_ / 128, M_ / 128, 1), 256, S1_SMEM>>>(
        xn, wqkv, nullptr, qkv, C_, C_, C_, 3 * C_,
        0, 0, 0, 0, 0, 0, 1, nullptr, nullptr, 0.f, nullptr, 0);

    // 3) scores = scale * q @ k^T, masked -> fp16 scores (halves write traffic)
    wgemm_abt<EPI_SCORE, 1><<<dim3(N_ / 128, N_ / 128, B_ * H_), 256, S1_SMEM>>>(
        qkv, qkv + C_, nullptr, ap, D_, 3 * C_, 3 * C_, N_,
        (long long)N_ * 3 * C_, D_,
        (long long)N_ * 3 * C_, D_,
        (long long)H_ * N_ * N_, (long long)N_ * N_,
        H_, nullptr, nullptr, scale, mask, N_);

    // 4) softmax: fp16 scores in -> fp32 attn out + fp16 probs (in place)
    softmax_hh_kernel<<<B_ * H_ * N_, 256>>>(ap, attn);

    // 5) ctx = attn @ v  (fp16)
    wgemm_ab64<<<dim3(1, N_ / 128, B_ * H_), 256, S2_SMEM>>>(
        ap, qkv + 2 * C_, ctx,
        N_, N_, 3 * C_, C_,
        (long long)H_ * N_ * N_, (long long)N_ * N_,
        (long long)N_ * 3 * C_, D_,
        (long long)N_ * C_, D_,
        H_);

    // 6) x1 = x + ctx @ proj_w^T + proj_b  (fp32)
    wgemm_abt<EPI_BIAS_RES, 0><<<dim3(C_ / 128, M_ / 128, 1), 256, S1_SMEM>>>(
        ctx, wproj, x1, nullptr, C_, C_, C_, C_,
        0, 0, 0, 0, 0, 0, 1, proj_b, x, 0.f, nullptr, 0);

    // 7) ln2 -> fp16
    ln_h_kernel<<<M_, 256>>>(x1, ln2_g, ln2_b, hn);

    // 8) ff = gelu(hn @ fc1_w^T + fc1_b)  (fp16)
    wgemm_abt<EPI_BIAS_GELU, 1><<<dim3(DFF / 128, M_ / 128, 1), 256, S1_SMEM>>>(
        hn, wfc1, nullptr, ff, C_, C_, C_, DFF,
        0, 0, 0, 0, 0, 0, 1, fc1_b, nullptr, 0.f, nullptr, 0);

    // 9) out_x = x1 + ff @ fc2_w^T + fc2_b  (fp32)
    wgemm_abt<EPI_BIAS_RES, 0><<<dim3(C_ / 128, M_ / 128, 1), 256, S1_SMEM>>>(
        ff, wfc2, out_x, nullptr, DFF, DFF, DFF, C_,
        0, 0, 0, 0, 0, 0, 1, fc2_b, x1, 0.f, nullptr, 0);
}